// round 13
// baseline (speedup 1.0000x reference)
#include <cuda_runtime.h>
#include <cuda_bf16.h>
#include <cstdint>

#define B_ 1024
#define T_ 200

typedef unsigned long long ull;
typedef unsigned int uint32;

// Scratch for x-projections: [3][T][B][128] fp32 (static device global, allowed).
__device__ float g_proj[(size_t)3 * T_ * B_ * 128];

// HW tanh (MUFU.TANH, sm_75+; base PTX feature).
__device__ __forceinline__ float tanh_hw(float x) {
    float t; asm("tanh.approx.f32 %0, %1;" : "=f"(t) : "f"(x)); return t;
}
__device__ __forceinline__ float sig_hw(float x) {
    return 0.5f * tanh_hw(0.5f * x) + 0.5f;
}

__device__ __forceinline__ uint32 pk_bf16(float a, float b) {
    return (uint32)__bfloat16_as_ushort(__float2bfloat16(a)) |
           ((uint32)__bfloat16_as_ushort(__float2bfloat16(b)) << 16);
}
__device__ __forceinline__ float bf16hi_res(float v, float& hi) {
    __nv_bfloat16 h = __float2bfloat16(v);
    hi = __bfloat162float(h);
    return v - hi;
}
__device__ __forceinline__ void mma_bf16(float& c0, float& c1, float& c2, float& c3,
                                         uint32 a0, uint32 a1, uint32 a2, uint32 a3,
                                         uint32 b0, uint32 b1) {
    asm volatile(
        "mma.sync.aligned.m16n8k16.row.col.f32.bf16.bf16.f32 "
        "{%0,%1,%2,%3}, {%4,%5,%6,%7}, {%8,%9}, {%0,%1,%2,%3};"
        : "+f"(c0), "+f"(c1), "+f"(c2), "+f"(c3)
        : "r"(a0), "r"(a1), "r"(a2), "r"(a3), "r"(b0), "r"(b1));
}

// ---------------------------------------------------------------------------
// Pass 1 (HMMA): g_proj = X @ W_top, bf16-split (hh+hl+lh), 512 threads,
// double-buffered X staging, ONE sync per tile.
// 16 warps: wr = w>>3 (2 row-groups of 16), wc = w&7 (8 col-groups of 48).
// ---------------------------------------------------------------------------
#define SW_OFF(row, word) (((uint32)(row) << 8) + ((((word) ^ (((row) & 7) << 2)) & 63) << 2))
__global__ __launch_bounds__(512, 1) void proj_kernel(
    const float* __restrict__ x,
    const float* __restrict__ Wu, const float* __restrict__ Wr,
    const float* __restrict__ Wc)
{
    extern __shared__ char smc[];
    // [0,196608): W hi(3)/lo(3); [196608 + p*16384): sXh, +8192: sXl
    const int tid  = threadIdx.x;
    const int w    = tid >> 5;
    const int lane = tid & 31;
    const int gr   = lane >> 2;
    const int gc   = lane & 3;
    const int wr   = w >> 3;            // 0..1
    const int wc   = w & 7;             // 0..7
    const int r0   = wr * 16;

    {
        const float* Ws[3] = {Wu, Wr, Wc};
        for (int m = 0; m < 3; ++m) {
            char* hb = smc + m * 32768;
            char* lb = smc + (3 + m) * 32768;
            for (int idx = tid; idx < 16384; idx += 512) {
                int k = idx >> 7, j = idx & 127;
                float v = Ws[m][idx];
                __nv_bfloat16 hbf = __float2bfloat16(v);
                float lres = v - __bfloat162float(hbf);
                uint32 off = SW_OFF(j, k >> 1) + (k & 1) * 2;
                *(__nv_bfloat16*)(hb + off) = hbf;
                *(__nv_bfloat16*)(lb + off) = __float2bfloat16(lres);
            }
        }
    }

    const float4* x4 = (const float4*)x;
    const int ntiles = (B_ * T_) / 32;     // 6400

    float4 xreg[2];
    int tile = blockIdx.x;
    if (tile < ntiles) {
#pragma unroll
        for (int c = 0; c < 2; ++c) xreg[c] = x4[(size_t)tile * 1024 + tid + c * 512];
    }
    int p = 0;

    for (; tile < ntiles; tile += gridDim.x) {
        // Stage current tile into buffer p (safe: all warps passed last sync
        // only after finishing compute on this buffer two iterations ago).
        char* bXh = smc + 196608 + p * 16384;
        char* bXl = bXh + 8192;
#pragma unroll
        for (int c = 0; c < 2; ++c) {
            int f = tid + c * 512;
            int r = f >> 5;
            int wd = (f & 31) * 2;
            float4 v = xreg[c];
            uint32 off = SW_OFF(r, wd);
            *(ull*)(bXh + off) = (ull)pk_bf16(v.x, v.y) | ((ull)pk_bf16(v.z, v.w) << 32);
            float lx = v.x - __bfloat162float(__float2bfloat16(v.x));
            float ly = v.y - __bfloat162float(__float2bfloat16(v.y));
            float lz = v.z - __bfloat162float(__float2bfloat16(v.z));
            float lw = v.w - __bfloat162float(__float2bfloat16(v.w));
            *(ull*)(bXl + off) = (ull)pk_bf16(lx, ly) | ((ull)pk_bf16(lz, lw) << 32);
        }
        __syncthreads();   // buffer p staged (also covers W init on iter 0)

        int ntile = tile + gridDim.x;
        if (ntile < ntiles) {
#pragma unroll
            for (int c = 0; c < 2; ++c) xreg[c] = x4[(size_t)ntile * 1024 + tid + c * 512];
        }

        float C[6][4];
#pragma unroll
        for (int n = 0; n < 6; ++n)
#pragma unroll
            for (int i = 0; i < 4; ++i) C[n][i] = 0.f;

#pragma unroll
        for (int kt = 0; kt < 8; ++kt) {
            const int kw = kt * 8 + gc;
            const uint32 oA0 = SW_OFF(r0 + gr,     kw);
            const uint32 oA1 = SW_OFF(r0 + gr + 8, kw);
            const uint32 oA2 = SW_OFF(r0 + gr,     kw + 4);
            const uint32 oA3 = SW_OFF(r0 + gr + 8, kw + 4);
            uint32 ah0 = *(const uint32*)(bXh + oA0);
            uint32 ah1 = *(const uint32*)(bXh + oA1);
            uint32 ah2 = *(const uint32*)(bXh + oA2);
            uint32 ah3 = *(const uint32*)(bXh + oA3);
            uint32 al0 = *(const uint32*)(bXl + oA0);
            uint32 al1 = *(const uint32*)(bXl + oA1);
            uint32 al2 = *(const uint32*)(bXl + oA2);
            uint32 al3 = *(const uint32*)(bXl + oA3);
#pragma unroll
            for (int nt = 0; nt < 6; ++nt) {
                int n0 = wc * 48 + nt * 8;
                int m  = n0 >> 7;
                int jb = (n0 & 127) + gr;
                const char* bh = smc + m * 32768;
                const char* bl = smc + (3 + m) * 32768;
                uint32 oB0 = SW_OFF(jb, kw);
                uint32 oB1 = SW_OFF(jb, kw + 4);
                uint32 bh0 = *(const uint32*)(bh + oB0);
                uint32 bh1 = *(const uint32*)(bh + oB1);
                uint32 bl0 = *(const uint32*)(bl + oB0);
                uint32 bl1 = *(const uint32*)(bl + oB1);
                mma_bf16(C[nt][0], C[nt][1], C[nt][2], C[nt][3],
                         ah0, ah1, ah2, ah3, bh0, bh1);
                mma_bf16(C[nt][0], C[nt][1], C[nt][2], C[nt][3],
                         ah0, ah1, ah2, ah3, bl0, bl1);
                mma_bf16(C[nt][0], C[nt][1], C[nt][2], C[nt][3],
                         al0, al1, al2, al3, bh0, bh1);
            }
        }

        const int ridA = tile * 32 + r0 + gr;
        const int ridB = ridA + 8;
        const int bA = ridA / T_, tA = ridA - bA * T_;
        const int bB = ridB / T_, tB = ridB - bB * T_;
#pragma unroll
        for (int nt = 0; nt < 6; ++nt) {
            int cgl = wc * 48 + nt * 8 + gc * 2;
            int m = cgl >> 7, j = cgl & 127;
            float* dA = g_proj + ((size_t)(m * T_ + tA) * B_ + bA) * 128 + j;
            float* dB = g_proj + ((size_t)(m * T_ + tB) * B_ + bB) * 128 + j;
            *(float2*)dA = make_float2(C[nt][0], C[nt][1]);
            *(float2*)dB = make_float2(C[nt][2], C[nt][3]);
        }
        p ^= 1;
    }
}

// ---------------------------------------------------------------------------
// Pass 2 (HMMA recurrence): 128 CTAs x 8 batch rows, 512 threads (16 warps).
// Warp w owns output cols [8w, 8w+8). Merged bf16 split (A rows 0-7 hi,
// 8-15 lo). Frag cell = uint4 (hi_k0, lo_k0, hi_k8, lo_k8); warp w writes the
// (w&1) 8-byte half of k-tile w>>1. Accumulators split by kt parity (chain
// depth 8). 48 MMAs/warp/step, 2 barriers/step.
// ---------------------------------------------------------------------------
__global__ __launch_bounds__(512, 1) void rec_kernel(
    const float* __restrict__ att,
    const void* __restrict__ slen_raw,
    const float* __restrict__ Wu, const float* __restrict__ Wr,
    const float* __restrict__ Wc,
    float* __restrict__ out)
{
    extern __shared__ char smr[];
    uint32* hfrag = (uint32*)smr;             // [8 kt][32 lane][4 u32]  4096 B
    uint32* sfrag = (uint32*)(smr + 4096);    // [8 kt][32 lane][4 u32]  4096 B
    uint32* blo   = (uint32*)(smr + 8192);    // [16w][3f][8kt][32][2]  98304 B
    __shared__ int s_is64;

    const int tid  = threadIdx.x;
    const int w    = tid >> 5;
    const int lane = tid & 31;
    const int qr   = lane >> 2;               // 0..7
    const int qc   = lane & 3;                // 0..3
    const int row  = blockIdx.x * 8 + qr;     // global batch row
    const int col0 = w * 8 + qc * 2;          // output cols col0, col0+1
    const uint32 fslot = ((w >> 1) * 32 + lane) * 4 + (w & 1) * 2;  // frag half

    // ---- B fragments: hi -> registers (3 groups), lo -> smem ----
    uint32 bhi[3][8][2];
#pragma unroll
    for (int f = 0; f < 3; ++f) {
        const float* Wsrc = (f == 0) ? Wu : (f == 1 ? Wr : Wc);
        const int n = w * 8 + qr;
#pragma unroll
        for (int kt = 0; kt < 8; ++kt) {
            int k = kt * 16 + qc * 2;
            float h00, h01, h10, h11;
            float l00 = bf16hi_res(Wsrc[16384 + k * 128 + n], h00);
            float l01 = bf16hi_res(Wsrc[16384 + (k + 1) * 128 + n], h01);
            float l10 = bf16hi_res(Wsrc[16384 + (k + 8) * 128 + n], h10);
            float l11 = bf16hi_res(Wsrc[16384 + (k + 9) * 128 + n], h11);
            bhi[f][kt][0] = pk_bf16(h00, h01);
            bhi[f][kt][1] = pk_bf16(h10, h11);
            uint32* dst = blo + (((w * 3 + f) * 8 + kt) * 32 + lane) * 2;
            dst[0] = pk_bf16(l00, l01);
            dst[1] = pk_bf16(l10, l11);
        }
    }
    for (int i = tid; i < 1024; i += 512) hfrag[i] = 0u;
    if (tid == 0) {
        const int* a = (const int*)slen_raw;   // int64 detection via high words
        s_is64 = (a[1] == 0 && a[3] == 0 && a[5] == 0 && a[7] == 0) ? 1 : 0;
    }
    __syncthreads();

    int sl;
    if (s_is64) sl = (int)((const long long*)slen_raw)[row];
    else        sl = ((const int*)slen_raw)[row];

    float h0 = 0.f, h1 = 0.f;   // h at (row, col0), (row, col0+1)

    for (int t = 0; t < T_; ++t) {
        // ---- phase 1: gate MMAs (f0=u, f1=r), parity-split accumulators ----
        float Dg[2][2][4];
#pragma unroll
        for (int f = 0; f < 2; ++f)
#pragma unroll
            for (int pp = 0; pp < 2; ++pp)
#pragma unroll
                for (int i = 0; i < 4; ++i) Dg[f][pp][i] = 0.f;

#pragma unroll
        for (int kt = 0; kt < 8; ++kt) {
            uint4 af = *(const uint4*)(hfrag + (kt * 32 + lane) * 4);
            const int pp = kt & 1;
#pragma unroll
            for (int f = 0; f < 2; ++f) {
                const uint32* bl = blo + (((w * 3 + f) * 8 + kt) * 32 + lane) * 2;
                uint32 bl0 = bl[0], bl1 = bl[1];
                mma_bf16(Dg[f][pp][0], Dg[f][pp][1], Dg[f][pp][2], Dg[f][pp][3],
                         af.x, af.y, af.z, af.w, bhi[f][kt][0], bhi[f][kt][1]);
                mma_bf16(Dg[f][pp][0], Dg[f][pp][1], Dg[f][pp][2], Dg[f][pp][3],
                         af.x, af.y, af.z, af.w, bl0, bl1);
            }
        }

        // ---- gate finalize ----
        const float* gp = g_proj + (size_t)t * B_ * 128 + (size_t)row * 128;
        float2 xu = *(const float2*)(gp + col0);
        float2 xr = *(const float2*)(gp + (size_t)T_ * B_ * 128 + col0);
        float u0 = sig_hw(Dg[0][0][0] + Dg[0][0][2] + Dg[0][1][0] + Dg[0][1][2] + xu.x);
        float u1 = sig_hw(Dg[0][0][1] + Dg[0][0][3] + Dg[0][1][1] + Dg[0][1][3] + xu.y);
        float s0 = sig_hw(Dg[1][0][0] + Dg[1][0][2] + Dg[1][1][0] + Dg[1][1][2] + xr.x) * h0;
        float s1 = sig_hw(Dg[1][0][1] + Dg[1][0][3] + Dg[1][1][1] + Dg[1][1][3] + xr.y) * h1;
        {
            float sh0, sh1;
            float sl0 = bf16hi_res(s0, sh0), sl1 = bf16hi_res(s1, sh1);
            *(uint2*)(sfrag + fslot) = make_uint2(pk_bf16(sh0, sh1), pk_bf16(sl0, sl1));
        }
        __syncthreads();   // s-fragments ready

        // ---- phase 2: candidate MMAs (f2=c) ----
        float Dc[2][4];
#pragma unroll
        for (int pp = 0; pp < 2; ++pp)
#pragma unroll
            for (int i = 0; i < 4; ++i) Dc[pp][i] = 0.f;

#pragma unroll
        for (int kt = 0; kt < 8; ++kt) {
            uint4 af = *(const uint4*)(sfrag + (kt * 32 + lane) * 4);
            const int pp = kt & 1;
            const uint32* bl = blo + (((w * 3 + 2) * 8 + kt) * 32 + lane) * 2;
            uint32 bl0 = bl[0], bl1 = bl[1];
            mma_bf16(Dc[pp][0], Dc[pp][1], Dc[pp][2], Dc[pp][3],
                     af.x, af.y, af.z, af.w, bhi[2][kt][0], bhi[2][kt][1]);
            mma_bf16(Dc[pp][0], Dc[pp][1], Dc[pp][2], Dc[pp][3],
                     af.x, af.y, af.z, af.w, bl0, bl1);
        }

        // ---- update ----
        float2 xc = *(const float2*)(gp + (size_t)2 * T_ * B_ * 128 + col0);
        float av = att[(size_t)row * T_ + t];
        bool live = (t < sl);
        {
            float ht0 = tanh_hw(Dc[0][0] + Dc[0][2] + Dc[1][0] + Dc[1][2] + xc.x);
            float ht1 = tanh_hw(Dc[0][1] + Dc[0][3] + Dc[1][1] + Dc[1][3] + xc.y);
            float n0 = h0 + u0 * av * (ht0 - h0);
            float n1 = h1 + u1 * av * (ht1 - h1);
            h0 = live ? n0 : h0;
            h1 = live ? n1 : h1;
        }
        *(float2*)(out + ((size_t)row * T_ + t) * 128 + col0) = make_float2(h0, h1);
        {
            float hh0, hh1;
            float hl0 = bf16hi_res(h0, hh0), hl1 = bf16hi_res(h1, hh1);
            *(uint2*)(hfrag + fslot) = make_uint2(pk_bf16(hh0, hh1), pk_bf16(hl0, hl1));
        }
        __syncthreads();   // h-fragments ready for next step
    }
}

// ---------------------------------------------------------------------------
extern "C" void kernel_launch(void* const* d_in, const int* in_sizes, int n_in,
                              void* d_out, int out_size)
{
    // Resolve inputs by element count (robust to metadata ordering).
    int iSeq = -1, iLen = -1, iAtt = -1, iW[3] = {-1, -1, -1};
    int nw = 0;
    for (int i = 0; i < n_in; ++i) {
        int s = in_sizes[i];
        if      (s == 26214400) iSeq = i;
        else if (s == 1024)     iLen = i;
        else if (s == 204800)   iAtt = i;
        else if (s == 32768 && nw < 3) iW[nw++] = i;
    }
    if (iSeq < 0 || iLen < 0 || iAtt < 0 || nw != 3) {
        iSeq = 0; iLen = 1; iAtt = 2; iW[0] = 3; iW[1] = 4; iW[2] = 5;
    }
    int iWu, iWr, iWc;
    if (iW[0] < iSeq) { iWc = iW[0]; iWr = iW[1]; iWu = iW[2]; }  // alphabetical
    else              { iWu = iW[0]; iWr = iW[1]; iWc = iW[2]; }  // insertion

    const float* seq_emb = (const float*)d_in[iSeq];
    const void*  slen    = d_in[iLen];
    const float* att     = (const float*)d_in[iAtt];
    const float* Wu      = (const float*)d_in[iWu];
    const float* Wr      = (const float*)d_in[iWr];
    const float* Wc      = (const float*)d_in[iWc];
    float*       out     = (float*)d_out;

    const int smem1 = 6 * 32768 + 4 * 8192;   // 229376 B (double-buffered X)
    const int smem2 = 8192 + 98304;           // 106496 B
    cudaFuncSetAttribute(proj_kernel, cudaFuncAttributeMaxDynamicSharedMemorySize, smem1);
    cudaFuncSetAttribute(rec_kernel,  cudaFuncAttributeMaxDynamicSharedMemorySize, smem2);

    proj_kernel<<<148, 512, smem1>>>(seq_emb, Wu, Wr, Wc);
    rec_kernel<<<128, 512, smem2>>>(att, slen, Wu, Wr, Wc, out);
}

// round 14
// speedup vs baseline: 1.3595x; 1.3595x over previous
#include <cuda_runtime.h>
#include <cuda_bf16.h>
#include <cstdint>

#define B_ 1024
#define T_ 200

typedef unsigned long long ull;
typedef unsigned int uint32;

// Scratch for x-projections: [3][T][B][128] fp32 (static device global, allowed).
__device__ float g_proj[(size_t)3 * T_ * B_ * 128];

// HW tanh (MUFU.TANH, sm_75+; base PTX feature).
__device__ __forceinline__ float tanh_hw(float x) {
    float t; asm("tanh.approx.f32 %0, %1;" : "=f"(t) : "f"(x)); return t;
}
__device__ __forceinline__ float sig_hw(float x) {
    return 0.5f * tanh_hw(0.5f * x) + 0.5f;
}

__device__ __forceinline__ uint32 pk_bf16(float a, float b) {
    return (uint32)__bfloat16_as_ushort(__float2bfloat16(a)) |
           ((uint32)__bfloat16_as_ushort(__float2bfloat16(b)) << 16);
}
__device__ __forceinline__ float bf16hi_res(float v, float& hi) {
    __nv_bfloat16 h = __float2bfloat16(v);
    hi = __bfloat162float(h);
    return v - hi;
}
__device__ __forceinline__ void mma_bf16(float& c0, float& c1, float& c2, float& c3,
                                         uint32 a0, uint32 a1, uint32 a2, uint32 a3,
                                         uint32 b0, uint32 b1) {
    asm volatile(
        "mma.sync.aligned.m16n8k16.row.col.f32.bf16.bf16.f32 "
        "{%0,%1,%2,%3}, {%4,%5,%6,%7}, {%8,%9}, {%0,%1,%2,%3};"
        : "+f"(c0), "+f"(c1), "+f"(c2), "+f"(c3)
        : "r"(a0), "r"(a1), "r"(a2), "r"(a3), "r"(b0), "r"(b1));
}

// ---------------------------------------------------------------------------
// Pass 1 (HMMA): g_proj = X @ W_top, bf16-split (hh+hl+lh), 256 threads.
// FRAGMENT-PACKED smem: W stored as MMA B-fragments
//   fragB[g 0..47][kt 0..7][lane] = uint4(bh0, bh1, bl0, bl1)
// and X staged as A-fragments
//   fragA{hi,lo}[rt 0..1][kt 0..7][lane] = uint4(a0, a1, a2, a3)
// -> compute loop: 1 LDS.128 per (nt,kt) + 2 LDS.128 per kt for A
//    (was 4+8 scalar LDS.32). All LDS.128 conflict-free.
// ---------------------------------------------------------------------------
__global__ __launch_bounds__(256, 1) void proj_kernel(
    const float* __restrict__ x,
    const float* __restrict__ Wu, const float* __restrict__ Wr,
    const float* __restrict__ Wc)
{
    extern __shared__ char smc[];
    // [0, 196608): fragB (48*8*32*16)
    // [196608, 204800): fragA_hi (2*8*32*16)
    // [204800, 212992): fragA_lo
    char* fB  = smc;
    char* fAh = smc + 196608;
    char* fAl = smc + 204800;
    const int tid  = threadIdx.x;
    const int w    = tid >> 5;
    const int lane = tid & 31;
    const int gr   = lane >> 2;
    const int gc   = lane & 3;
    const int wr   = w >> 2;            // row-group 0..1
    const int wc   = w & 3;             // col-group 0..3 (12 n-tiles each)

    // ---- build fragB from W (top halves), coalesced over j ----
    {
        const float* Ws[3] = {Wu, Wr, Wc};
        for (int idx = tid; idx < 24576; idx += 256) {
            int j  = idx & 127;
            int kp = (idx >> 7) & 63;      // k pair index, k = 2*kp
            int m  = idx >> 13;
            int k  = kp * 2;
            const float* W = Ws[m];
            float h0, h1;
            float l0 = bf16hi_res(W[k * 128 + j], h0);
            float l1 = bf16hi_res(W[(k + 1) * 128 + j], h1);
            int g   = m * 16 + (j >> 3);
            int grr = j & 7;
            int kt  = k >> 4;
            int qcc = (k & 7) >> 1;
            int hi8 = (k & 8) >> 3;        // 0: b0 slot, 1: b1 slot
            char* cell = fB + (((g * 8 + kt) * 32 + grr * 4 + qcc) << 4);
            *(uint32*)(cell + hi8 * 4)     = pk_bf16(h0, h1);   // bh0/bh1
            *(uint32*)(cell + 8 + hi8 * 4) = pk_bf16(l0, l1);   // bl0/bl1
        }
    }

    const float4* x4 = (const float4*)x;
    const int ntiles = (B_ * T_) / 32;     // 6400

    float4 xreg[4];
    int tile = blockIdx.x;
    if (tile < ntiles) {
#pragma unroll
        for (int c = 0; c < 4; ++c) xreg[c] = x4[(size_t)tile * 1024 + tid + c * 256];
    }

    for (; tile < ntiles; tile += gridDim.x) {
        __syncthreads();   // previous tile's readers done (covers fragB init)
        // ---- stage X into A-fragment layout ----
#pragma unroll
        for (int c = 0; c < 4; ++c) {
            int f = tid + c * 256;
            int r = f >> 5;                // 0..31
            int k0 = (f & 31) * 4;
            float4 v = xreg[c];
            int rt = r >> 4, rr = r & 15;
            int grr = rr & 7;
            int rowslot = rr >> 3;         // 0 -> a0/a2, 1 -> a1/a3
#pragma unroll
            for (int p_ = 0; p_ < 2; ++p_) {
                int kk = k0 + 2 * p_;
                float e = (p_ == 0) ? v.x : v.z;
                float o = (p_ == 0) ? v.y : v.w;
                int kt  = kk >> 4;
                int qcc = (kk & 7) >> 1;
                int fld = rowslot + (((kk & 8) >> 3) << 1);   // 0..3
                uint32 off = (((rt * 8 + kt) * 32 + grr * 4 + qcc) << 4) + fld * 4;
                float hhe, hho;
                float le = bf16hi_res(e, hhe);
                float lo_ = bf16hi_res(o, hho);
                *(uint32*)(fAh + off) = pk_bf16(hhe, hho);
                *(uint32*)(fAl + off) = pk_bf16(le, lo_);
            }
        }
        __syncthreads();   // fragA ready

        int ntile = tile + gridDim.x;
        if (ntile < ntiles) {
#pragma unroll
            for (int c = 0; c < 4; ++c) xreg[c] = x4[(size_t)ntile * 1024 + tid + c * 256];
        }

        float C[12][4];
#pragma unroll
        for (int n = 0; n < 12; ++n)
#pragma unroll
            for (int i = 0; i < 4; ++i) C[n][i] = 0.f;

#pragma unroll
        for (int kt = 0; kt < 8; ++kt) {
            const uint32 aoff = ((wr * 8 + kt) * 32 + lane) << 4;
            uint4 Ah = *(const uint4*)(fAh + aoff);
            uint4 Al = *(const uint4*)(fAl + aoff);
#pragma unroll
            for (int nt = 0; nt < 12; ++nt) {
                int g = wc * 12 + nt;
                uint4 Bf = *(const uint4*)(fB + (((g * 8 + kt) * 32 + lane) << 4));
                mma_bf16(C[nt][0], C[nt][1], C[nt][2], C[nt][3],
                         Ah.x, Ah.y, Ah.z, Ah.w, Bf.x, Bf.y);
                mma_bf16(C[nt][0], C[nt][1], C[nt][2], C[nt][3],
                         Ah.x, Ah.y, Ah.z, Ah.w, Bf.z, Bf.w);
                mma_bf16(C[nt][0], C[nt][1], C[nt][2], C[nt][3],
                         Al.x, Al.y, Al.z, Al.w, Bf.x, Bf.y);
            }
        }

        const int ridA = tile * 32 + wr * 16 + gr;
        const int ridB = ridA + 8;
        const int bA = ridA / T_, tA = ridA - bA * T_;
        const int bB = ridB / T_, tB = ridB - bB * T_;
#pragma unroll
        for (int nt = 0; nt < 12; ++nt) {
            int cgl = wc * 96 + nt * 8 + gc * 2;
            int m = cgl >> 7, j = cgl & 127;
            float* dA = g_proj + ((size_t)(m * T_ + tA) * B_ + bA) * 128 + j;
            float* dB = g_proj + ((size_t)(m * T_ + tB) * B_ + bB) * 128 + j;
            *(float2*)dA = make_float2(C[nt][0], C[nt][1]);
            *(float2*)dB = make_float2(C[nt][2], C[nt][3]);
        }
    }
}

// ---------------------------------------------------------------------------
// Pass 2 (HMMA recurrence): REVERTED to round-12 version (known 382us).
// 128 CTAs x 8 batch rows, 256 threads (8 warps), warp w owns cols [16w,16w+16).
// Merged bf16 split (A rows 0-7 hi, 8-15 lo); 96 MMAs/warp/step; HW tanh;
// 2 barriers/step.
// ---------------------------------------------------------------------------
__global__ __launch_bounds__(256, 1) void rec_kernel(
    const float* __restrict__ att,
    const void* __restrict__ slen_raw,
    const float* __restrict__ Wu, const float* __restrict__ Wr,
    const float* __restrict__ Wc,
    float* __restrict__ out)
{
    extern __shared__ char smr[];
    uint32* hfrag = (uint32*)smr;             // [8 kt][32 lane][4 u32]  4096 B
    uint32* sfrag = (uint32*)(smr + 4096);    // [8 kt][32 lane][4 u32]  4096 B
    uint32* blo   = (uint32*)(smr + 8192);    // [48 g][8 kt][32 lane][2 u32] 98304 B
    __shared__ int s_is64;

    const int tid  = threadIdx.x;
    const int w    = tid >> 5;
    const int lane = tid & 31;
    const int qr   = lane >> 2;
    const int qc   = lane & 3;
    const int row  = blockIdx.x * 8 + qr;
    const int colA = w * 16 + qc * 2;
    const int colB = colA + 8;

    uint32 bhi[6][8][2];
#pragma unroll
    for (int f = 0; f < 6; ++f) {
        const float* Wsrc = (f < 2) ? Wu : (f < 4 ? Wr : Wc);
        const int n = w * 16 + (f & 1) * 8 + qr;
#pragma unroll
        for (int kt = 0; kt < 8; ++kt) {
            int k = kt * 16 + qc * 2;
            float h00, h01, h10, h11;
            float l00 = bf16hi_res(Wsrc[16384 + k * 128 + n], h00);
            float l01 = bf16hi_res(Wsrc[16384 + (k + 1) * 128 + n], h01);
            float l10 = bf16hi_res(Wsrc[16384 + (k + 8) * 128 + n], h10);
            float l11 = bf16hi_res(Wsrc[16384 + (k + 9) * 128 + n], h11);
            bhi[f][kt][0] = pk_bf16(h00, h01);
            bhi[f][kt][1] = pk_bf16(h10, h11);
            uint32* dst = blo + (((w * 6 + f) * 8 + kt) * 32 + lane) * 2;
            dst[0] = pk_bf16(l00, l01);
            dst[1] = pk_bf16(l10, l11);
        }
    }
    for (int i = tid; i < 1024; i += 256) hfrag[i] = 0u;
    if (tid == 0) {
        const int* a = (const int*)slen_raw;
        s_is64 = (a[1] == 0 && a[3] == 0 && a[5] == 0 && a[7] == 0) ? 1 : 0;
    }
    __syncthreads();

    int sl;
    if (s_is64) sl = (int)((const long long*)slen_raw)[row];
    else        sl = ((const int*)slen_raw)[row];

    float h0 = 0.f, h1 = 0.f, h2 = 0.f, h3 = 0.f;

    for (int t = 0; t < T_; ++t) {
        float Dg[4][4];
#pragma unroll
        for (int f = 0; f < 4; ++f)
#pragma unroll
            for (int i = 0; i < 4; ++i) Dg[f][i] = 0.f;

#pragma unroll
        for (int kt = 0; kt < 8; ++kt) {
            uint4 af = *(const uint4*)(hfrag + (kt * 32 + lane) * 4);
#pragma unroll
            for (int f = 0; f < 4; ++f) {
                const uint32* bl = blo + (((w * 6 + f) * 8 + kt) * 32 + lane) * 2;
                uint32 bl0 = bl[0], bl1 = bl[1];
                mma_bf16(Dg[f][0], Dg[f][1], Dg[f][2], Dg[f][3],
                         af.x, af.z, af.y, af.w, bhi[f][kt][0], bhi[f][kt][1]);
                mma_bf16(Dg[f][0], Dg[f][1], Dg[f][2], Dg[f][3],
                         af.x, af.z, af.y, af.w, bl0, bl1);
            }
        }

        const float* gp = g_proj + (size_t)t * B_ * 128 + (size_t)row * 128;
        float2 xuA = *(const float2*)(gp + colA);
        float2 xuB = *(const float2*)(gp + colB);
        float2 xrA = *(const float2*)(gp + (size_t)T_ * B_ * 128 + colA);
        float2 xrB = *(const float2*)(gp + (size_t)T_ * B_ * 128 + colB);
        float uA0 = sig_hw(Dg[0][0] + Dg[0][2] + xuA.x);
        float uA1 = sig_hw(Dg[0][1] + Dg[0][3] + xuA.y);
        float uB0 = sig_hw(Dg[1][0] + Dg[1][2] + xuB.x);
        float uB1 = sig_hw(Dg[1][1] + Dg[1][3] + xuB.y);
        float sA0 = sig_hw(Dg[2][0] + Dg[2][2] + xrA.x) * h0;
        float sA1 = sig_hw(Dg[2][1] + Dg[2][3] + xrA.y) * h1;
        float sB0 = sig_hw(Dg[3][0] + Dg[3][2] + xrB.x) * h2;
        float sB1 = sig_hw(Dg[3][1] + Dg[3][3] + xrB.y) * h3;
        {
            float hA0, hA1, hB0, hB1;
            float lA0 = bf16hi_res(sA0, hA0), lA1 = bf16hi_res(sA1, hA1);
            float lB0 = bf16hi_res(sB0, hB0), lB1 = bf16hi_res(sB1, hB1);
            uint4 sf;
            sf.x = pk_bf16(hA0, hA1); sf.y = pk_bf16(hB0, hB1);
            sf.z = pk_bf16(lA0, lA1); sf.w = pk_bf16(lB0, lB1);
            *(uint4*)(sfrag + (w * 32 + lane) * 4) = sf;
        }
        __syncthreads();

        float Dc[2][4];
#pragma unroll
        for (int f = 0; f < 2; ++f)
#pragma unroll
            for (int i = 0; i < 4; ++i) Dc[f][i] = 0.f;

#pragma unroll
        for (int kt = 0; kt < 8; ++kt) {
            uint4 af = *(const uint4*)(sfrag + (kt * 32 + lane) * 4);
#pragma unroll
            for (int f = 0; f < 2; ++f) {
                const uint32* bl = blo + (((w * 6 + 4 + f) * 8 + kt) * 32 + lane) * 2;
                uint32 bl0 = bl[0], bl1 = bl[1];
                mma_bf16(Dc[f][0], Dc[f][1], Dc[f][2], Dc[f][3],
                         af.x, af.z, af.y, af.w, bhi[4 + f][kt][0], bhi[4 + f][kt][1]);
                mma_bf16(Dc[f][0], Dc[f][1], Dc[f][2], Dc[f][3],
                         af.x, af.z, af.y, af.w, bl0, bl1);
            }
        }

        float2 xcA = *(const float2*)(gp + (size_t)2 * T_ * B_ * 128 + colA);
        float2 xcB = *(const float2*)(gp + (size_t)2 * T_ * B_ * 128 + colB);
        float av = att[(size_t)row * T_ + t];
        bool live = (t < sl);
        {
            float htA0 = tanh_hw(Dc[0][0] + Dc[0][2] + xcA.x);
            float htA1 = tanh_hw(Dc[0][1] + Dc[0][3] + xcA.y);
            float htB0 = tanh_hw(Dc[1][0] + Dc[1][2] + xcB.x);
            float htB1 = tanh_hw(Dc[1][1] + Dc[1][3] + xcB.y);
            float n0 = h0 + uA0 * av * (htA0 - h0);
            float n1 = h1 + uA1 * av * (htA1 - h1);
            float n2 = h2 + uB0 * av * (htB0 - h2);
            float n3 = h3 + uB1 * av * (htB1 - h3);
            h0 = live ? n0 : h0;
            h1 = live ? n1 : h1;
            h2 = live ? n2 : h2;
            h3 = live ? n3 : h3;
        }
        float* op = out + ((size_t)row * T_ + t) * 128;
        *(float2*)(op + colA) = make_float2(h0, h1);
        *(float2*)(op + colB) = make_float2(h2, h3);
        {
            float hA0, hA1, hB0, hB1;
            float lA0 = bf16hi_res(h0, hA0), lA1 = bf16hi_res(h1, hA1);
            float lB0 = bf16hi_res(h2, hB0), lB1 = bf16hi_res(h3, hB1);
            uint4 hf;
            hf.x = pk_bf16(hA0, hA1); hf.y = pk_bf16(hB0, hB1);
            hf.z = pk_bf16(lA0, lA1); hf.w = pk_bf16(lB0, lB1);
            *(uint4*)(hfrag + (w * 32 + lane) * 4) = hf;
        }
        __syncthreads();
    }
}

// ---------------------------------------------------------------------------
extern "C" void kernel_launch(void* const* d_in, const int* in_sizes, int n_in,
                              void* d_out, int out_size)
{
    // Resolve inputs by element count (robust to metadata ordering).
    int iSeq = -1, iLen = -1, iAtt = -1, iW[3] = {-1, -1, -1};
    int nw = 0;
    for (int i = 0; i < n_in; ++i) {
        int s = in_sizes[i];
        if      (s == 26214400) iSeq = i;
        else if (s == 1024)     iLen = i;
        else if (s == 204800)   iAtt = i;
        else if (s == 32768 && nw < 3) iW[nw++] = i;
    }
    if (iSeq < 0 || iLen < 0 || iAtt < 0 || nw != 3) {
        iSeq = 0; iLen = 1; iAtt = 2; iW[0] = 3; iW[1] = 4; iW[2] = 5;
    }
    int iWu, iWr, iWc;
    if (iW[0] < iSeq) { iWc = iW[0]; iWr = iW[1]; iWu = iW[2]; }  // alphabetical
    else              { iWu = iW[0]; iWr = iW[1]; iWc = iW[2]; }  // insertion

    const float* seq_emb = (const float*)d_in[iSeq];
    const void*  slen    = d_in[iLen];
    const float* att     = (const float*)d_in[iAtt];
    const float* Wu      = (const float*)d_in[iWu];
    const float* Wr      = (const float*)d_in[iWr];
    const float* Wc      = (const float*)d_in[iWc];
    float*       out     = (float*)d_out;

    const int smem1 = 196608 + 2 * 8192;      // 212992 B
    const int smem2 = 8192 + 98304;           // 106496 B
    cudaFuncSetAttribute(proj_kernel, cudaFuncAttributeMaxDynamicSharedMemorySize, smem1);
    cudaFuncSetAttribute(rec_kernel,  cudaFuncAttributeMaxDynamicSharedMemorySize, smem2);

    proj_kernel<<<148, 256, smem1>>>(seq_emb, Wu, Wr, Wc);
    rec_kernel<<<128, 256, smem2>>>(att, slen, Wu, Wr, Wc, out);
}